// round 12
// baseline (speedup 1.0000x reference)
#include <cuda_runtime.h>
#include <cuda_bf16.h>
#include <math.h>
#include <stdint.h>

#define NN    6912                 // nodes
#define NE    82944                // edges (no self loops)
#define NE2   89856                // edges + self loops
#define DV    96                   // per-node feature width
#define TOT   (NN*DV)              // 663552 output elements
#define HIDW  384
#define WSLOT (384*384)

// ---------------- scratch (static device globals; no allocs) ----------------
__device__ __align__(128) float g_hB[NN*DV];
__device__ __align__(128) float g_buf[NN*DV];
__device__ __align__(128) float g_res[TOT];
__device__ __align__(128) float g_xl[NN*HIDW];
__device__ __align__(128) float g_xr[NN*HIDW];
__device__ __align__(128) float g_logits[NE2*4];
__device__ __align__(128) __nv_bfloat16 g_ah[NN*HIDW];
__device__ __align__(128) __nv_bfloat16 g_al[NN*HIDW];
__device__ __align__(128) __nv_bfloat16 g_bh[NN*HIDW];
__device__ __align__(128) __nv_bfloat16 g_bl[NN*HIDW];
__device__ __align__(128) __nv_bfloat16 g_wbh[10*WSLOT];
__device__ __align__(128) __nv_bfloat16 g_wbl[10*WSLOT];
__device__ int    g_off[NN+1];
__device__ int    g_cur[NN];
__device__ int    g_deg[NN];
__device__ int    g_csrc[NE2];
__device__ double g_stat[2];

// ---- build h0: bf16 hi/lo (Kpad=128) + residual + edge count + stat init ---
__global__ void k_build_h0(const float* __restrict__ x, const float* __restrict__ cf,
                           const int* __restrict__ ei) {
    int i = blockIdx.x*blockDim.x + threadIdx.x;
    if (i == 0) { g_stat[0] = 0.0; g_stat[1] = 0.0; }
    if (i < NE) atomicAdd(&g_deg[ei[NE + i]], 1);
    if (i >= NN*128) return;
    int row = i >> 7;
    int col = i & 127;
    float v = 0.f;
    if (col < 32)      v = x[row*32 + col];
    else if (col < 96) v = cf[(row/27)*64 + (col - 32)];
    __nv_bfloat16 h = __float2bfloat16(v);
    g_ah[i] = h;
    g_al[i] = __float2bfloat16(v - __bfloat162float(h));
    if (col < 96) g_res[row*96 + col] = v;
}

// ---- single-block scan (adds +1 self loop per node, re-zeros g_deg) --------
__global__ void k_scan() {
    __shared__ int wsum[32], wbase[32];
    __shared__ int stot;
    int tid = threadIdx.x, lane = tid & 31, wid = tid >> 5;
    int base = tid*7;
    int v[7]; int s = 0;
    #pragma unroll
    for (int j = 0; j < 7; j++) {
        int i = base + j;
        v[j] = (i < NN) ? (g_deg[i] + 1) : 0;
        s += v[j];
    }
    int incl = s;
    #pragma unroll
    for (int o = 1; o < 32; o <<= 1) {
        int t = __shfl_up_sync(0xffffffffu, incl, o);
        if (lane >= o) incl += t;
    }
    if (lane == 31) wsum[wid] = incl;
    __syncthreads();
    if (wid == 0) {
        int x = wsum[lane];
        int xi = x;
        #pragma unroll
        for (int o = 1; o < 32; o <<= 1) {
            int t = __shfl_up_sync(0xffffffffu, xi, o);
            if (lane >= o) xi += t;
        }
        wbase[lane] = xi - x;
        if (lane == 31) stot = xi;
    }
    __syncthreads();
    int ex = wbase[wid] + (incl - s);
    #pragma unroll
    for (int j = 0; j < 7; j++) {
        int i = base + j;
        if (i < NN) { g_off[i] = ex; g_cur[i] = ex; g_deg[i] = 0; }
        ex += v[j];
    }
    if (tid == 0) g_off[NN] = stot;
}

__global__ void k_scatter(const int* __restrict__ ei) {
    int i = blockIdx.x*blockDim.x + threadIdx.x;
    if (i >= NE2) return;
    int s, d;
    if (i < NE) { s = ei[i]; d = ei[NE + i]; }
    else        { s = i - NE; d = s; }
    int pos = atomicAdd(&g_cur[d], 1);
    g_csrc[pos] = s;
}

// ---- all 10 weights -> hi/lo bf16 [Nc,Kpad] transposed, one launch ---------
__global__ void k_cvtw_all(const float* __restrict__ Wlf, const float* __restrict__ Wrf,
        const float* __restrict__ Wli, const float* __restrict__ Wri,
        const float* __restrict__ Wll, const float* __restrict__ Wrl) {
    int s = blockIdx.z;
    int l = s >> 1, m = s & 1;
    int K    = (l == 0) ? 96  : 384;
    int Kpad = (l == 0) ? 128 : 384;
    int Nc   = (l == 4) ? 96  : 384;
    const float* src;
    if (l == 0)      src = m ? Wrf : Wlf;
    else if (l == 4) src = m ? Wrl : Wll;
    else             src = (m ? Wri : Wli) + (size_t)(l-1)*WSLOT;
    int i = blockIdx.x*blockDim.x + threadIdx.x;
    if (i >= Nc*Kpad) return;
    int n = i / Kpad, k = i - n*Kpad;
    float v = (k < K) ? src[(size_t)k*Nc + n] : 0.f;
    __nv_bfloat16 h = __float2bfloat16(v);
    g_wbh[(size_t)s*WSLOT + i] = h;
    g_wbl[(size_t)s*WSLOT + i] = __float2bfloat16(v - __bfloat162float(h));
}

// ---- cp.async double-buffered mma.sync bf16 split GEMM (dynamic smem) ------
#define KC 32
#define APITCH 40
#define TILEB (128*APITCH)
#define SMEM_GEMM (8*TILEB*2)       // 81920 B

__device__ __forceinline__ void mma16816(float* c, const uint32_t* a,
                                         uint32_t b0, uint32_t b1) {
    asm volatile(
        "mma.sync.aligned.m16n8k16.row.col.f32.bf16.bf16.f32 "
        "{%0,%1,%2,%3},{%4,%5,%6,%7},{%8,%9},{%0,%1,%2,%3};"
        : "+f"(c[0]), "+f"(c[1]), "+f"(c[2]), "+f"(c[3])
        : "r"(a[0]), "r"(a[1]), "r"(a[2]), "r"(a[3]), "r"(b0), "r"(b1));
}
__device__ __forceinline__ void cpa16(uint32_t dst, const void* src, int nbytes) {
    asm volatile("cp.async.cg.shared.global [%0], [%1], 16, %2;"
        :: "r"(dst), "l"(src), "r"(nbytes));
}

__global__ void __launch_bounds__(256) k_mmagemm(
        const __nv_bfloat16* __restrict__ Ah, const __nv_bfloat16* __restrict__ Al,
        const __nv_bfloat16* __restrict__ B1h, const __nv_bfloat16* __restrict__ B1l,
        const __nv_bfloat16* __restrict__ B2h, const __nv_bfloat16* __restrict__ B2l,
        float* __restrict__ C1, float* __restrict__ C2,
        int Kg, int Nc, int ntiles) {
    extern __shared__ __nv_bfloat16 smg[];
    __nv_bfloat16* Asm = smg;
    __nv_bfloat16* Bsm = smg + 4*TILEB;
    int tid = threadIdx.x, wid = tid >> 5, lane = tid & 31;
    int mat = blockIdx.x / ntiles;
    int n0  = (blockIdx.x - mat*ntiles) * 128;
    int m0  = blockIdx.y * 128;
    int Nt  = min(128, Nc - n0);
    const __nv_bfloat16* Bh = mat ? B2h : B1h;
    const __nv_bfloat16* Bl = mat ? B2l : B1l;
    float* C = mat ? C2 : C1;
    int warp_m = wid & 3, warp_n = wid >> 2;
    int gid = lane >> 2, tig = lane & 3;

    uint32_t aBase, bBase;
    asm("{ .reg .u64 t; cvta.to.shared.u64 t, %1; cvt.u32.u64 %0, t; }"
        : "=r"(aBase) : "l"(Asm));
    asm("{ .reg .u64 t; cvta.to.shared.u64 t, %1; cvt.u32.u64 %0, t; }"
        : "=r"(bBase) : "l"(Bsm));

    float acc[2][8][4];
    #pragma unroll
    for (int mt = 0; mt < 2; mt++)
        #pragma unroll
        for (int nt = 0; nt < 8; nt++)
            #pragma unroll
            for (int j = 0; j < 4; j++) acc[mt][nt][j] = 0.f;

    int nch = Kg / KC;
    int r0g = tid >> 2, q0g = tid & 3;
    #define ISSUE(c_, st_) do { \
        int _k0 = (c_)*KC; \
        uint32_t _sb = (uint32_t)(st_)*(2*TILEB*2); \
        _Pragma("unroll") \
        for (int _j = 0; _j < 2; _j++) { \
            int _r = r0g + _j*64, _q = q0g; \
            uint32_t _off = _sb + (uint32_t)(_r*APITCH + _q*8)*2; \
            size_t _ga = (size_t)(m0 + _r)*Kg + _k0 + _q*8; \
            cpa16(aBase + _off,           Ah + _ga, 16); \
            cpa16(aBase + _off + TILEB*2, Al + _ga, 16); \
            int _vb = (n0 + _r < Nc) ? 16 : 0; \
            size_t _gb = (size_t)(n0 + _r)*Kg + _k0 + _q*8; \
            cpa16(bBase + _off,           Bh + _gb, _vb); \
            cpa16(bBase + _off + TILEB*2, Bl + _gb, _vb); \
        } \
        asm volatile("cp.async.commit_group;"); \
    } while (0)

    ISSUE(0, 0);
    for (int c = 0; c < nch; c++) {
        int st = c & 1;
        if (c + 1 < nch) {
            ISSUE(c + 1, st ^ 1);
            asm volatile("cp.async.wait_group 1;");
        } else {
            asm volatile("cp.async.wait_group 0;");
        }
        __syncthreads();
        const __nv_bfloat16* Ast0 = Asm + st*2*TILEB;
        const __nv_bfloat16* Bst0 = Bsm + st*2*TILEB;
        #pragma unroll
        for (int ks = 0; ks < 2; ks++) {
            int cb = ks*16 + tig*2;
            uint32_t afr[2][2][4];
            #pragma unroll
            for (int mt = 0; mt < 2; mt++) {
                int r0 = warp_m*32 + mt*16 + gid;
                #pragma unroll
                for (int hl = 0; hl < 2; hl++) {
                    const __nv_bfloat16* bp = Ast0 + hl*TILEB;
                    afr[mt][hl][0] = *(const uint32_t*)&bp[r0*APITCH + cb];
                    afr[mt][hl][1] = *(const uint32_t*)&bp[(r0+8)*APITCH + cb];
                    afr[mt][hl][2] = *(const uint32_t*)&bp[r0*APITCH + cb + 8];
                    afr[mt][hl][3] = *(const uint32_t*)&bp[(r0+8)*APITCH + cb + 8];
                }
            }
            #pragma unroll
            for (int nt = 0; nt < 8; nt++) {
                int n = warp_n*64 + nt*8 + gid;
                uint32_t bh0 = *(const uint32_t*)&Bst0[n*APITCH + cb];
                uint32_t bh1 = *(const uint32_t*)&Bst0[n*APITCH + cb + 8];
                uint32_t bl0 = *(const uint32_t*)&Bst0[TILEB + n*APITCH + cb];
                uint32_t bl1 = *(const uint32_t*)&Bst0[TILEB + n*APITCH + cb + 8];
                #pragma unroll
                for (int mt = 0; mt < 2; mt++) {
                    mma16816(acc[mt][nt], afr[mt][0], bh0, bh1);
                    mma16816(acc[mt][nt], afr[mt][0], bl0, bl1);
                    mma16816(acc[mt][nt], afr[mt][1], bh0, bh1);
                }
            }
        }
        __syncthreads();
    }

    #pragma unroll
    for (int nt = 0; nt < 8; nt++) {
        int nc = warp_n*64 + nt*8;
        if (nc >= Nt) continue;
        int col = n0 + nc + tig*2;
        #pragma unroll
        for (int mt = 0; mt < 2; mt++) {
            int row = m0 + warp_m*32 + mt*16 + gid;
            *(float2*)(C + (size_t)row*Nc + col) =
                make_float2(acc[mt][nt][0], acc[mt][nt][1]);
            *(float2*)(C + (size_t)(row+8)*Nc + col) =
                make_float2(acc[mt][nt][2], acc[mt][nt][3]);
        }
    }
}

// ---- attention logits: block per dst node, 4-edge unroll for MLP -----------
__global__ void k_logits2(const float* __restrict__ xl, const float* __restrict__ xr,
        const float* __restrict__ att, int H) {
    int b = blockIdx.x;
    int h = threadIdx.x >> 5, lane = threadIdx.x & 31;
    int W = H * 96;
    int c = h*96 + lane;
    float xr0 = xr[(size_t)b*W + c];
    float xr1 = xr[(size_t)b*W + c + 32];
    float xr2 = xr[(size_t)b*W + c + 64];
    float at0 = __ldg(att + c);
    float at1 = __ldg(att + c + 32);
    float at2 = __ldg(att + c + 64);
    int e  = g_off[b];
    int e1 = g_off[b+1];
    for (; e + 4 <= e1; e += 4) {
        float u[4];
        #pragma unroll
        for (int j = 0; j < 4; j++) {
            const float* p = xl + (size_t)g_csrc[e+j]*W + h*96;
            float v0 = p[lane] + xr0, v1 = p[lane+32] + xr1, v2 = p[lane+64] + xr2;
            v0 = v0 > 0.f ? v0 : 0.2f*v0;
            v1 = v1 > 0.f ? v1 : 0.2f*v1;
            v2 = v2 > 0.f ? v2 : 0.2f*v2;
            u[j] = fmaf(at0, v0, fmaf(at1, v1, at2*v2));
        }
        #pragma unroll
        for (int o = 16; o; o >>= 1) {
            u[0] += __shfl_xor_sync(0xffffffffu, u[0], o);
            u[1] += __shfl_xor_sync(0xffffffffu, u[1], o);
            u[2] += __shfl_xor_sync(0xffffffffu, u[2], o);
            u[3] += __shfl_xor_sync(0xffffffffu, u[3], o);
        }
        if (lane == 0) {
            #pragma unroll
            for (int j = 0; j < 4; j++) g_logits[(size_t)(e+j)*H + h] = u[j];
        }
    }
    for (; e < e1; e++) {
        const float* p = xl + (size_t)g_csrc[e]*W + h*96;
        float v0 = p[lane] + xr0, v1 = p[lane+32] + xr1, v2 = p[lane+64] + xr2;
        v0 = v0 > 0.f ? v0 : 0.2f*v0;
        v1 = v1 > 0.f ? v1 : 0.2f*v1;
        v2 = v2 > 0.f ? v2 : 0.2f*v2;
        float u = fmaf(at0, v0, fmaf(at1, v1, at2*v2));
        #pragma unroll
        for (int o = 16; o; o >>= 1) u += __shfl_xor_sync(0xffffffffu, u, o);
        if (lane == 0) g_logits[(size_t)e*H + h] = u;
    }
}

// ---- per-dst softmax + aggregation; epilogue writes bf16 hi/lo or fp32 -----
__global__ void k_agg(const float* __restrict__ xl, const float* __restrict__ bias,
        float* __restrict__ outF, __nv_bfloat16* __restrict__ oh,
        __nv_bfloat16* __restrict__ ol, int H, int flags) {
    int b   = blockIdx.x;
    int tid = threadIdx.x;
    int W   = blockDim.x;
    int h   = tid / 96;
    int lane = tid & 31, wid = tid >> 5;
    int e0 = g_off[b], deg = g_off[b+1] - e0;

    __shared__ float s_m[4], s_id[4];
    if (wid < H) {
        float m = -1e30f;
        for (int i = lane; i < deg; i += 32)
            m = fmaxf(m, g_logits[(size_t)(e0+i)*H + wid]);
        #pragma unroll
        for (int o = 16; o; o >>= 1) m = fmaxf(m, __shfl_xor_sync(0xffffffffu, m, o));
        float ss = 0.f;
        for (int i = lane; i < deg; i += 32)
            ss += __expf(g_logits[(size_t)(e0+i)*H + wid] - m);
        #pragma unroll
        for (int o = 16; o; o >>= 1) ss += __shfl_xor_sync(0xffffffffu, ss, o);
        if (lane == 0) { s_m[wid] = m; s_id[wid] = 1.f/ss; }
    }
    __syncthreads();

    __shared__ float s_alpha[4*96];
    __shared__ int   s_src[96];
    float a0 = 0.f, a1 = 0.f, a2 = 0.f, a3 = 0.f;
    for (int base = 0; base < deg; base += 96) {
        int cn = min(96, deg - base);
        if (tid < cn) s_src[tid] = g_csrc[e0 + base + tid];
        if (wid < H) {
            float m = s_m[wid], id = s_id[wid];
            for (int i = lane; i < cn; i += 32)
                s_alpha[wid*96 + i] =
                    __expf(g_logits[(size_t)(e0 + base + i)*H + wid] - m) * id;
        }
        __syncthreads();
        int i = 0;
        for (; i + 4 <= cn; i += 4) {
            a0 = fmaf(s_alpha[h*96 + i],     xl[(size_t)s_src[i]  *W + tid], a0);
            a1 = fmaf(s_alpha[h*96 + i + 1], xl[(size_t)s_src[i+1]*W + tid], a1);
            a2 = fmaf(s_alpha[h*96 + i + 2], xl[(size_t)s_src[i+2]*W + tid], a2);
            a3 = fmaf(s_alpha[h*96 + i + 3], xl[(size_t)s_src[i+3]*W + tid], a3);
        }
        for (; i < cn; i++)
            a0 = fmaf(s_alpha[h*96 + i], xl[(size_t)s_src[i]*W + tid], a0);
        __syncthreads();
    }
    float o = (a0 + a1) + (a2 + a3) + __ldg(bias + tid);
    o = o > 0.f ? o : 0.01f*o;
    size_t oi = (size_t)b*W + tid;
    if (flags & 2) outF[oi] = o;
    if (flags & 1) {
        __nv_bfloat16 hi = __float2bfloat16(o);
        oh[oi] = hi;
        ol[oi] = __float2bfloat16(o - __bfloat162float(hi));
    }
}

// ---- residual add + LN statistics ------------------------------------------
__global__ void k_resred(const float* __restrict__ h5, float* __restrict__ buf) {
    double s = 0.0, s2 = 0.0;
    for (int i = blockIdx.x*blockDim.x + threadIdx.x; i < TOT;
         i += gridDim.x*blockDim.x) {
        float v = h5[i] + g_res[i];
        buf[i] = v;
        s  += (double)v;
        s2 += (double)v * (double)v;
    }
    #pragma unroll
    for (int o = 16; o; o >>= 1) {
        s  += __shfl_xor_sync(0xffffffffu, s,  o);
        s2 += __shfl_xor_sync(0xffffffffu, s2, o);
    }
    __shared__ double sh[8], sh2[8];
    int lane = threadIdx.x & 31, wid = threadIdx.x >> 5;
    if (lane == 0) { sh[wid] = s; sh2[wid] = s2; }
    __syncthreads();
    if (wid == 0) {
        int nw = blockDim.x >> 5;
        s  = (lane < nw) ? sh[lane]  : 0.0;
        s2 = (lane < nw) ? sh2[lane] : 0.0;
        #pragma unroll
        for (int o = 4; o; o >>= 1) {
            s  += __shfl_xor_sync(0xffffffffu, s,  o);
            s2 += __shfl_xor_sync(0xffffffffu, s2, o);
        }
        if (lane == 0) { atomicAdd(&g_stat[0], s); atomicAdd(&g_stat[1], s2); }
    }
}

__global__ void k_final(const float* __restrict__ buf, const float* __restrict__ w,
        const float* __restrict__ bb, float* __restrict__ out) {
    double mu  = g_stat[0] / (double)TOT;
    double var = g_stat[1] / (double)TOT - mu*mu;
    float rs  = (float)(1.0 / sqrt(var + 1e-5));
    float fmu = (float)mu;
    for (int i = blockIdx.x*blockDim.x + threadIdx.x; i < TOT;
         i += gridDim.x*blockDim.x) {
        int c = i % DV;
        out[i] = (buf[i] - fmu) * rs * w[c] + bb[c];
    }
}

// ---- launch -----------------------------------------------------------------
extern "C" void kernel_launch(void* const* d_in, const int* in_sizes, int n_in,
                              void* d_out, int out_size) {
    const float* circ     = (const float*)d_in[0];
    const float* x        = (const float*)d_in[1];
    const int*   ei       = (const int*)d_in[2];
    const float* Wl_first = (const float*)d_in[3];
    const float* Wr_first = (const float*)d_in[4];
    const float* att_first= (const float*)d_in[5];
    const float* b_first  = (const float*)d_in[6];
    const float* Wl_inner = (const float*)d_in[7];
    const float* Wr_inner = (const float*)d_in[8];
    const float* att_inner= (const float*)d_in[9];
    const float* b_inner  = (const float*)d_in[10];
    const float* Wl_last  = (const float*)d_in[11];
    const float* Wr_last  = (const float*)d_in[12];
    const float* att_last = (const float*)d_in[13];
    const float* b_last   = (const float*)d_in[14];
    const float* ln_w     = (const float*)d_in[15];
    const float* ln_b     = (const float*)d_in[16];
    float*       outp     = (float*)d_out;

    float *hB, *buf, *xl, *xr;
    __nv_bfloat16 *ah, *al, *bh, *bl, *wbh, *wbl;
    cudaGetSymbolAddress((void**)&hB,  g_hB);
    cudaGetSymbolAddress((void**)&buf, g_buf);
    cudaGetSymbolAddress((void**)&xl,  g_xl);
    cudaGetSymbolAddress((void**)&xr,  g_xr);
    cudaGetSymbolAddress((void**)&ah,  g_ah);
    cudaGetSymbolAddress((void**)&al,  g_al);
    cudaGetSymbolAddress((void**)&bh,  g_bh);
    cudaGetSymbolAddress((void**)&bl,  g_bl);
    cudaGetSymbolAddress((void**)&wbh, g_wbh);
    cudaGetSymbolAddress((void**)&wbl, g_wbl);

    static int smem_set = 0;
    if (!smem_set) {
        cudaFuncSetAttribute(k_mmagemm,
            cudaFuncAttributeMaxDynamicSharedMemorySize, SMEM_GEMM);
        smem_set = 1;
    }

    k_build_h0<<<(NN*128 + 255)/256, 256>>>(x, circ, ei);
    k_scan    <<<1, 1024>>>();
    k_scatter <<<(NE2 + 255)/256, 256>>>(ei);
    k_cvtw_all<<<dim3(576, 1, 10), 256>>>(Wl_first, Wr_first, Wl_inner,
                                          Wr_inner, Wl_last, Wr_last);

    const float* atts[5] = {att_first, att_inner, att_inner + 384,
                            att_inner + 2*384, att_last};
    const float* bs[5]   = {b_first, b_inner, b_inner + 384, b_inner + 2*384, b_last};
    int Kpads[5] = {128, 384, 384, 384, 384};
    int Ncs[5]   = {384, 384, 384, 384, 96};
    int Hs[5]    = {4, 4, 4, 4, 1};

    __nv_bfloat16* inh = ah;  __nv_bfloat16* inl = al;
    __nv_bfloat16* oth = bh;  __nv_bfloat16* otl = bl;
    for (int l = 0; l < 5; l++) {
        int W = Hs[l]*96;
        int ntiles = (Ncs[l] + 127)/128;
        k_mmagemm<<<dim3(ntiles*2, NN/128), 256, SMEM_GEMM>>>(
            inh, inl,
            wbh + (size_t)(2*l)*WSLOT,   wbl + (size_t)(2*l)*WSLOT,
            wbh + (size_t)(2*l+1)*WSLOT, wbl + (size_t)(2*l+1)*WSLOT,
            xl, xr, Kpads[l], Ncs[l], ntiles);
        k_logits2<<<NN, 32*Hs[l]>>>(xl, xr, atts[l], Hs[l]);
        int flags = (l < 4) ? 1 : 2;
        k_agg<<<NN, W>>>(xl, bs[l], hB, oth, otl, Hs[l], flags);
        __nv_bfloat16* th = inh; inh = oth; oth = th;
        __nv_bfloat16* tl = inl; inl = otl; otl = tl;
    }
    k_resred<<<512, 256>>>(hB, buf);
    k_final <<<(TOT + 255)/256, 256>>>(buf, ln_w, ln_b, outp);
}

// round 14
// speedup vs baseline: 1.0287x; 1.0287x over previous
#include <cuda_runtime.h>
#include <cuda_bf16.h>
#include <math.h>
#include <stdint.h>

#define NN    6912                 // nodes
#define NE    82944                // edges (no self loops)
#define NE2   89856                // edges + self loops
#define DV    96                   // per-node feature width
#define TOT   (NN*DV)              // 663552 output elements
#define HIDW  384
#define WSLOT (384*384)
#define PREPB 3456                 // blocks for h0 region (NN*128/256)

// ---------------- scratch (static device globals; no allocs) ----------------
__device__ __align__(128) float g_hB[NN*DV];
__device__ __align__(128) float g_buf[NN*DV];
__device__ __align__(128) float g_res[TOT];
__device__ __align__(128) float g_xl[NN*HIDW];
__device__ __align__(128) float g_xr[NN*HIDW];
__device__ __align__(128) float g_logits[NE2*4];
__device__ __align__(128) __nv_bfloat16 g_ah[NN*HIDW];
__device__ __align__(128) __nv_bfloat16 g_al[NN*HIDW];
__device__ __align__(128) __nv_bfloat16 g_bh[NN*HIDW];
__device__ __align__(128) __nv_bfloat16 g_bl[NN*HIDW];
__device__ __align__(128) __nv_bfloat16 g_wbh[10*WSLOT];
__device__ __align__(128) __nv_bfloat16 g_wbl[10*WSLOT];
__device__ int    g_off[NN+1];
__device__ int    g_cur[NN];
__device__ int    g_deg[NN];
__device__ int    g_csrc[NE2];
__device__ double g_stat[2];

// ---- fused prep: h0 build + edge count + stat init + all weight converts ---
__global__ void k_prep(const float* __restrict__ x, const float* __restrict__ cf,
        const int* __restrict__ ei,
        const float* __restrict__ Wlf, const float* __restrict__ Wrf,
        const float* __restrict__ Wli, const float* __restrict__ Wri,
        const float* __restrict__ Wll, const float* __restrict__ Wrl) {
    int bid = blockIdx.x;
    if (bid < PREPB) {
        int i = bid*256 + threadIdx.x;
        if (i == 0) { g_stat[0] = 0.0; g_stat[1] = 0.0; }
        if (i < NE) atomicAdd(&g_deg[ei[NE + i]], 1);
        if (i >= NN*128) return;
        int row = i >> 7;
        int col = i & 127;
        float v = 0.f;
        if (col < 32)      v = x[row*32 + col];
        else if (col < 96) v = cf[(row/27)*64 + (col - 32)];
        __nv_bfloat16 h = __float2bfloat16(v);
        g_ah[i] = h;
        g_al[i] = __float2bfloat16(v - __bfloat162float(h));
        if (col < 96) g_res[row*96 + col] = v;
    } else {
        int j = bid - PREPB;
        int s = j / 576;
        int l = s >> 1, m = s & 1;
        int K    = (l == 0) ? 96  : 384;
        int Kpad = (l == 0) ? 128 : 384;
        int Nc   = (l == 4) ? 96  : 384;
        const float* src;
        if (l == 0)      src = m ? Wrf : Wlf;
        else if (l == 4) src = m ? Wrl : Wll;
        else             src = (m ? Wri : Wli) + (size_t)(l-1)*WSLOT;
        int i = (j - s*576)*256 + threadIdx.x;
        if (i >= Nc*Kpad) return;
        int n = i / Kpad, k = i - n*Kpad;
        float v = (k < K) ? src[(size_t)k*Nc + n] : 0.f;
        __nv_bfloat16 h = __float2bfloat16(v);
        g_wbh[(size_t)s*WSLOT + i] = h;
        g_wbl[(size_t)s*WSLOT + i] = __float2bfloat16(v - __bfloat162float(h));
    }
}

// ---- single-block scan (adds +1 self loop per node, re-zeros g_deg) --------
__global__ void k_scan() {
    __shared__ int wsum[32], wbase[32];
    __shared__ int stot;
    int tid = threadIdx.x, lane = tid & 31, wid = tid >> 5;
    int base = tid*7;
    int v[7]; int s = 0;
    #pragma unroll
    for (int j = 0; j < 7; j++) {
        int i = base + j;
        v[j] = (i < NN) ? (g_deg[i] + 1) : 0;
        s += v[j];
    }
    int incl = s;
    #pragma unroll
    for (int o = 1; o < 32; o <<= 1) {
        int t = __shfl_up_sync(0xffffffffu, incl, o);
        if (lane >= o) incl += t;
    }
    if (lane == 31) wsum[wid] = incl;
    __syncthreads();
    if (wid == 0) {
        int x = wsum[lane];
        int xi = x;
        #pragma unroll
        for (int o = 1; o < 32; o <<= 1) {
            int t = __shfl_up_sync(0xffffffffu, xi, o);
            if (lane >= o) xi += t;
        }
        wbase[lane] = xi - x;
        if (lane == 31) stot = xi;
    }
    __syncthreads();
    int ex = wbase[wid] + (incl - s);
    #pragma unroll
    for (int j = 0; j < 7; j++) {
        int i = base + j;
        if (i < NN) { g_off[i] = ex; g_cur[i] = ex; g_deg[i] = 0; }
        ex += v[j];
    }
    if (tid == 0) g_off[NN] = stot;
}

__global__ void k_scatter(const int* __restrict__ ei) {
    int i = blockIdx.x*blockDim.x + threadIdx.x;
    if (i >= NE2) return;
    int s, d;
    if (i < NE) { s = ei[i]; d = ei[NE + i]; }
    else        { s = i - NE; d = s; }
    int pos = atomicAdd(&g_cur[d], 1);
    g_csrc[pos] = s;
}

// ---- cp.async double-buffered mma.sync bf16 split GEMM (dynamic smem) ------
#define KC 32
#define APITCH 40
#define TILEB (128*APITCH)
#define SMEM_GEMM (8*TILEB*2)       // 81920 B

__device__ __forceinline__ void mma16816(float* c, const uint32_t* a,
                                         uint32_t b0, uint32_t b1) {
    asm volatile(
        "mma.sync.aligned.m16n8k16.row.col.f32.bf16.bf16.f32 "
        "{%0,%1,%2,%3},{%4,%5,%6,%7},{%8,%9},{%0,%1,%2,%3};"
        : "+f"(c[0]), "+f"(c[1]), "+f"(c[2]), "+f"(c[3])
        : "r"(a[0]), "r"(a[1]), "r"(a[2]), "r"(a[3]), "r"(b0), "r"(b1));
}
__device__ __forceinline__ void cpa16(uint32_t dst, const void* src, int nbytes) {
    asm volatile("cp.async.cg.shared.global [%0], [%1], 16, %2;"
        :: "r"(dst), "l"(src), "r"(nbytes));
}

__global__ void __launch_bounds__(256) k_mmagemm(
        const __nv_bfloat16* __restrict__ Ah, const __nv_bfloat16* __restrict__ Al,
        const __nv_bfloat16* __restrict__ B1h, const __nv_bfloat16* __restrict__ B1l,
        const __nv_bfloat16* __restrict__ B2h, const __nv_bfloat16* __restrict__ B2l,
        float* __restrict__ C1, float* __restrict__ C2,
        int Kg, int Nc, int ntiles) {
    extern __shared__ __nv_bfloat16 smg[];
    __nv_bfloat16* Asm = smg;
    __nv_bfloat16* Bsm = smg + 4*TILEB;
    int tid = threadIdx.x, wid = tid >> 5, lane = tid & 31;
    int mat = blockIdx.x / ntiles;
    int n0  = (blockIdx.x - mat*ntiles) * 128;
    int m0  = blockIdx.y * 128;
    int Nt  = min(128, Nc - n0);
    const __nv_bfloat16* Bh = mat ? B2h : B1h;
    const __nv_bfloat16* Bl = mat ? B2l : B1l;
    float* C = mat ? C2 : C1;
    int warp_m = wid & 3, warp_n = wid >> 2;
    int gid = lane >> 2, tig = lane & 3;

    uint32_t aBase, bBase;
    asm("{ .reg .u64 t; cvta.to.shared.u64 t, %1; cvt.u32.u64 %0, t; }"
        : "=r"(aBase) : "l"(Asm));
    asm("{ .reg .u64 t; cvta.to.shared.u64 t, %1; cvt.u32.u64 %0, t; }"
        : "=r"(bBase) : "l"(Bsm));

    float acc[2][8][4];
    #pragma unroll
    for (int mt = 0; mt < 2; mt++)
        #pragma unroll
        for (int nt = 0; nt < 8; nt++)
            #pragma unroll
            for (int j = 0; j < 4; j++) acc[mt][nt][j] = 0.f;

    int nch = Kg / KC;
    int r0g = tid >> 2, q0g = tid & 3;
    #define ISSUE(c_, st_) do { \
        int _k0 = (c_)*KC; \
        uint32_t _sb = (uint32_t)(st_)*(2*TILEB*2); \
        _Pragma("unroll") \
        for (int _j = 0; _j < 2; _j++) { \
            int _r = r0g + _j*64, _q = q0g; \
            uint32_t _off = _sb + (uint32_t)(_r*APITCH + _q*8)*2; \
            size_t _ga = (size_t)(m0 + _r)*Kg + _k0 + _q*8; \
            cpa16(aBase + _off,           Ah + _ga, 16); \
            cpa16(aBase + _off + TILEB*2, Al + _ga, 16); \
            int _vb = (n0 + _r < Nc) ? 16 : 0; \
            size_t _gb = (size_t)(n0 + _r)*Kg + _k0 + _q*8; \
            cpa16(bBase + _off,           Bh + _gb, _vb); \
            cpa16(bBase + _off + TILEB*2, Bl + _gb, _vb); \
        } \
        asm volatile("cp.async.commit_group;"); \
    } while (0)

    ISSUE(0, 0);
    for (int c = 0; c < nch; c++) {
        int st = c & 1;
        if (c + 1 < nch) {
            ISSUE(c + 1, st ^ 1);
            asm volatile("cp.async.wait_group 1;");
        } else {
            asm volatile("cp.async.wait_group 0;");
        }
        __syncthreads();
        const __nv_bfloat16* Ast0 = Asm + st*2*TILEB;
        const __nv_bfloat16* Bst0 = Bsm + st*2*TILEB;
        #pragma unroll
        for (int ks = 0; ks < 2; ks++) {
            int cb = ks*16 + tig*2;
            uint32_t afr[2][2][4];
            #pragma unroll
            for (int mt = 0; mt < 2; mt++) {
                int r0 = warp_m*32 + mt*16 + gid;
                #pragma unroll
                for (int hl = 0; hl < 2; hl++) {
                    const __nv_bfloat16* bp = Ast0 + hl*TILEB;
                    afr[mt][hl][0] = *(const uint32_t*)&bp[r0*APITCH + cb];
                    afr[mt][hl][1] = *(const uint32_t*)&bp[(r0+8)*APITCH + cb];
                    afr[mt][hl][2] = *(const uint32_t*)&bp[r0*APITCH + cb + 8];
                    afr[mt][hl][3] = *(const uint32_t*)&bp[(r0+8)*APITCH + cb + 8];
                }
            }
            #pragma unroll
            for (int nt = 0; nt < 8; nt++) {
                int n = warp_n*64 + nt*8 + gid;
                uint32_t bh0 = *(const uint32_t*)&Bst0[n*APITCH + cb];
                uint32_t bh1 = *(const uint32_t*)&Bst0[n*APITCH + cb + 8];
                uint32_t bl0 = *(const uint32_t*)&Bst0[TILEB + n*APITCH + cb];
                uint32_t bl1 = *(const uint32_t*)&Bst0[TILEB + n*APITCH + cb + 8];
                #pragma unroll
                for (int mt = 0; mt < 2; mt++) {
                    mma16816(acc[mt][nt], afr[mt][0], bh0, bh1);
                    mma16816(acc[mt][nt], afr[mt][0], bl0, bl1);
                    mma16816(acc[mt][nt], afr[mt][1], bh0, bh1);
                }
            }
        }
        __syncthreads();
    }

    #pragma unroll
    for (int nt = 0; nt < 8; nt++) {
        int nc = warp_n*64 + nt*8;
        if (nc >= Nt) continue;
        int col = n0 + nc + tig*2;
        #pragma unroll
        for (int mt = 0; mt < 2; mt++) {
            int row = m0 + warp_m*32 + mt*16 + gid;
            *(float2*)(C + (size_t)row*Nc + col) =
                make_float2(acc[mt][nt][0], acc[mt][nt][1]);
            *(float2*)(C + (size_t)(row+8)*Nc + col) =
                make_float2(acc[mt][nt][2], acc[mt][nt][3]);
        }
    }
}

// ---- attention logits: block per dst node, 2-edge unroll for MLP -----------
__global__ void k_logits2(const float* __restrict__ xl, const float* __restrict__ xr,
        const float* __restrict__ att, int H) {
    int b = blockIdx.x;
    int h = threadIdx.x >> 5, lane = threadIdx.x & 31;
    int W = H * 96;
    int c = h*96 + lane;
    float xr0 = xr[(size_t)b*W + c];
    float xr1 = xr[(size_t)b*W + c + 32];
    float xr2 = xr[(size_t)b*W + c + 64];
    float at0 = __ldg(att + c);
    float at1 = __ldg(att + c + 32);
    float at2 = __ldg(att + c + 64);
    int e  = g_off[b];
    int e1 = g_off[b+1];
    for (; e + 2 <= e1; e += 2) {
        const float* p0 = xl + (size_t)g_csrc[e]  *W + h*96;
        const float* p1 = xl + (size_t)g_csrc[e+1]*W + h*96;
        float a0 = p0[lane], a1 = p0[lane+32], a2 = p0[lane+64];
        float b0 = p1[lane], b1 = p1[lane+32], b2 = p1[lane+64];
        a0 += xr0; a1 += xr1; a2 += xr2;
        b0 += xr0; b1 += xr1; b2 += xr2;
        a0 = a0 > 0.f ? a0 : 0.2f*a0;
        a1 = a1 > 0.f ? a1 : 0.2f*a1;
        a2 = a2 > 0.f ? a2 : 0.2f*a2;
        b0 = b0 > 0.f ? b0 : 0.2f*b0;
        b1 = b1 > 0.f ? b1 : 0.2f*b1;
        b2 = b2 > 0.f ? b2 : 0.2f*b2;
        float u = fmaf(at0, a0, fmaf(at1, a1, at2*a2));
        float v = fmaf(at0, b0, fmaf(at1, b1, at2*b2));
        #pragma unroll
        for (int o = 16; o; o >>= 1) {
            u += __shfl_xor_sync(0xffffffffu, u, o);
            v += __shfl_xor_sync(0xffffffffu, v, o);
        }
        if (lane == 0) {
            g_logits[(size_t)e*H + h]     = u;
            g_logits[(size_t)(e+1)*H + h] = v;
        }
    }
    if (e < e1) {
        const float* p0 = xl + (size_t)g_csrc[e]*W + h*96;
        float a0 = p0[lane] + xr0, a1 = p0[lane+32] + xr1, a2 = p0[lane+64] + xr2;
        a0 = a0 > 0.f ? a0 : 0.2f*a0;
        a1 = a1 > 0.f ? a1 : 0.2f*a1;
        a2 = a2 > 0.f ? a2 : 0.2f*a2;
        float u = fmaf(at0, a0, fmaf(at1, a1, at2*a2));
        #pragma unroll
        for (int o = 16; o; o >>= 1) u += __shfl_xor_sync(0xffffffffu, u, o);
        if (lane == 0) g_logits[(size_t)e*H + h] = u;
    }
}

// ---- per-dst softmax + aggregation; epilogue writes bf16 hi/lo or fp32 -----
__global__ void k_agg(const float* __restrict__ xl, const float* __restrict__ bias,
        float* __restrict__ outF, __nv_bfloat16* __restrict__ oh,
        __nv_bfloat16* __restrict__ ol, int H, int flags) {
    int b   = blockIdx.x;
    int tid = threadIdx.x;
    int W   = blockDim.x;
    int h   = tid / 96;
    int lane = tid & 31, wid = tid >> 5;
    int e0 = g_off[b], deg = g_off[b+1] - e0;

    __shared__ float s_m[4], s_id[4];
    if (wid < H) {
        float m = -1e30f;
        for (int i = lane; i < deg; i += 32)
            m = fmaxf(m, g_logits[(size_t)(e0+i)*H + wid]);
        #pragma unroll
        for (int o = 16; o; o >>= 1) m = fmaxf(m, __shfl_xor_sync(0xffffffffu, m, o));
        float ss = 0.f;
        for (int i = lane; i < deg; i += 32)
            ss += __expf(g_logits[(size_t)(e0+i)*H + wid] - m);
        #pragma unroll
        for (int o = 16; o; o >>= 1) ss += __shfl_xor_sync(0xffffffffu, ss, o);
        if (lane == 0) { s_m[wid] = m; s_id[wid] = 1.f/ss; }
    }
    __syncthreads();

    __shared__ float s_alpha[4*96];
    __shared__ int   s_src[96];
    float a0 = 0.f, a1 = 0.f;
    for (int base = 0; base < deg; base += 96) {
        int cn = min(96, deg - base);
        if (tid < cn) s_src[tid] = g_csrc[e0 + base + tid];
        if (wid < H) {
            float m = s_m[wid], id = s_id[wid];
            for (int i = lane; i < cn; i += 32)
                s_alpha[wid*96 + i] =
                    __expf(g_logits[(size_t)(e0 + base + i)*H + wid] - m) * id;
        }
        __syncthreads();
        int i = 0;
        for (; i + 2 <= cn; i += 2) {
            a0 = fmaf(s_alpha[h*96 + i],     xl[(size_t)s_src[i]  *W + tid], a0);
            a1 = fmaf(s_alpha[h*96 + i + 1], xl[(size_t)s_src[i+1]*W + tid], a1);
        }
        if (i < cn) a0 = fmaf(s_alpha[h*96 + i], xl[(size_t)s_src[i]*W + tid], a0);
        __syncthreads();
    }
    float o = a0 + a1 + __ldg(bias + tid);
    o = o > 0.f ? o : 0.01f*o;
    size_t oi = (size_t)b*W + tid;
    if (flags & 2) outF[oi] = o;
    if (flags & 1) {
        __nv_bfloat16 hi = __float2bfloat16(o);
        oh[oi] = hi;
        ol[oi] = __float2bfloat16(o - __bfloat162float(hi));
    }
}

// ---- residual add + LN statistics ------------------------------------------
__global__ void k_resred(const float* __restrict__ h5, float* __restrict__ buf) {
    double s = 0.0, s2 = 0.0;
    for (int i = blockIdx.x*blockDim.x + threadIdx.x; i < TOT;
         i += gridDim.x*blockDim.x) {
        float v = h5[i] + g_res[i];
        buf[i] = v;
        s  += (double)v;
        s2 += (double)v * (double)v;
    }
    #pragma unroll
    for (int o = 16; o; o >>= 1) {
        s  += __shfl_xor_sync(0xffffffffu, s,  o);
        s2 += __shfl_xor_sync(0xffffffffu, s2, o);
    }
    __shared__ double sh[8], sh2[8];
    int lane = threadIdx.x & 31, wid = threadIdx.x >> 5;
    if (lane == 0) { sh[wid] = s; sh2[wid] = s2; }
    __syncthreads();
    if (wid == 0) {
        int nw = blockDim.x >> 5;
        s  = (lane < nw) ? sh[lane]  : 0.0;
        s2 = (lane < nw) ? sh2[lane] : 0.0;
        #pragma unroll
        for (int o = 4; o; o >>= 1) {
            s  += __shfl_xor_sync(0xffffffffu, s,  o);
            s2 += __shfl_xor_sync(0xffffffffu, s2, o);
        }
        if (lane == 0) { atomicAdd(&g_stat[0], s); atomicAdd(&g_stat[1], s2); }
    }
}

__global__ void k_final(const float* __restrict__ buf, const float* __restrict__ w,
        const float* __restrict__ bb, float* __restrict__ out) {
    double mu  = g_stat[0] / (double)TOT;
    double var = g_stat[1] / (double)TOT - mu*mu;
    float rs  = (float)(1.0 / sqrt(var + 1e-5));
    float fmu = (float)mu;
    for (int i = blockIdx.x*blockDim.x + threadIdx.x; i < TOT;
         i += gridDim.x*blockDim.x) {
        int c = i % DV;
        out[i] = (buf[i] - fmu) * rs * w[c] + bb[c];
    }
}

// ---- launch -----------------------------------------------------------------
extern "C" void kernel_launch(void* const* d_in, const int* in_sizes, int n_in,
                              void* d_out, int out_size) {
    const float* circ     = (const float*)d_in[0];
    const float* x        = (const float*)d_in[1];
    const int*   ei       = (const int*)d_in[2];
    const float* Wl_first = (const float*)d_in[3];
    const float* Wr_first = (const float*)d_in[4];
    const float* att_first= (const float*)d_in[5];
    const float* b_first  = (const float*)d_in[6];
    const float* Wl_inner = (const float*)d_in[7];
    const float* Wr_inner = (const float*)d_in[8];
    const float* att_inner= (const float*)d_in[9];
    const float* b_inner  = (const float*)d_in[10];
    const float* Wl_last  = (const float*)d_in[11];
    const float* Wr_last  = (const float*)d_in[12];
    const float* att_last = (const float*)d_in[13];
    const float* b_last   = (const float*)d_in[14];
    const float* ln_w     = (const float*)d_in[15];
    const float* ln_b     = (const float*)d_in[16];
    float*       outp     = (float*)d_out;

    float *hB, *buf, *xl, *xr;
    __nv_bfloat16 *ah, *al, *bh, *bl, *wbh, *wbl;
    cudaGetSymbolAddress((void**)&hB,  g_hB);
    cudaGetSymbolAddress((void**)&buf, g_buf);
    cudaGetSymbolAddress((void**)&xl,  g_xl);
    cudaGetSymbolAddress((void**)&xr,  g_xr);
    cudaGetSymbolAddress((void**)&ah,  g_ah);
    cudaGetSymbolAddress((void**)&al,  g_al);
    cudaGetSymbolAddress((void**)&bh,  g_bh);
    cudaGetSymbolAddress((void**)&bl,  g_bl);
    cudaGetSymbolAddress((void**)&wbh, g_wbh);
    cudaGetSymbolAddress((void**)&wbl, g_wbl);

    static int smem_set = 0;
    if (!smem_set) {
        cudaFuncSetAttribute(k_mmagemm,
            cudaFuncAttributeMaxDynamicSharedMemorySize, SMEM_GEMM);
        smem_set = 1;
    }

    k_prep   <<<PREPB + 5760, 256>>>(x, circ, ei, Wl_first, Wr_first,
                                     Wl_inner, Wr_inner, Wl_last, Wr_last);
    k_scan   <<<1, 1024>>>();
    k_scatter<<<(NE2 + 255)/256, 256>>>(ei);

    const float* atts[5] = {att_first, att_inner, att_inner + 384,
                            att_inner + 2*384, att_last};
    const float* bs[5]   = {b_first, b_inner, b_inner + 384, b_inner + 2*384, b_last};
    int Kpads[5] = {128, 384, 384, 384, 384};
    int Ncs[5]   = {384, 384, 384, 384, 96};
    int Hs[5]    = {4, 4, 4, 4, 1};

    __nv_bfloat16* inh = ah;  __nv_bfloat16* inl = al;
    __nv_bfloat16* oth = bh;  __nv_bfloat16* otl = bl;
    for (int l = 0; l < 5; l++) {
        int W = Hs[l]*96;
        int ntiles = (Ncs[l] + 127)/128;
        k_mmagemm<<<dim3(ntiles*2, NN/128), 256, SMEM_GEMM>>>(
            inh, inl,
            wbh + (size_t)(2*l)*WSLOT,   wbl + (size_t)(2*l)*WSLOT,
            wbh + (size_t)(2*l+1)*WSLOT, wbl + (size_t)(2*l+1)*WSLOT,
            xl, xr, Kpads[l], Ncs[l], ntiles);
        k_logits2<<<NN, 32*Hs[l]>>>(xl, xr, atts[l], Hs[l]);
        int flags = (l < 4) ? 1 : 2;
        k_agg<<<NN, W>>>(xl, bs[l], hB, oth, otl, Hs[l], flags);
        __nv_bfloat16* th = inh; inh = oth; oth = th;
        __nv_bfloat16* tl = inl; inl = otl; otl = tl;
    }
    k_resred<<<512, 256>>>(hB, buf);
    k_final <<<(TOT + 255)/256, 256>>>(buf, ln_w, ln_b, outp);
}

// round 15
// speedup vs baseline: 1.0464x; 1.0172x over previous
#include <cuda_runtime.h>
#include <cuda_bf16.h>
#include <math.h>
#include <stdint.h>

#define NN    6912                 // nodes
#define NE    82944                // edges (no self loops)
#define NE2   89856                // edges + self loops
#define DV    96                   // per-node feature width
#define TOT   (NN*DV)              // 663552 output elements
#define HIDW  384
#define WSLOT (384*384)
#define PREPB 3456                 // blocks for h0 region (NN*128/256)

// ---------------- scratch (static device globals; no allocs) ----------------
__device__ __align__(128) float g_hB[NN*DV];
__device__ __align__(128) float g_buf[NN*DV];
__device__ __align__(128) float g_res[TOT];
__device__ __align__(128) float g_xl[NN*HIDW];
__device__ __align__(128) float g_xr[NN*HIDW];
__device__ __align__(128) float g_logits[NE2*4];
__device__ __align__(128) __nv_bfloat16 g_ah[NN*HIDW];
__device__ __align__(128) __nv_bfloat16 g_al[NN*HIDW];
__device__ __align__(128) __nv_bfloat16 g_bh[NN*HIDW];
__device__ __align__(128) __nv_bfloat16 g_bl[NN*HIDW];
__device__ __align__(128) __nv_bfloat16 g_wbh[10*WSLOT];
__device__ __align__(128) __nv_bfloat16 g_wbl[10*WSLOT];
__device__ int    g_off[NN+1];
__device__ int    g_cur[NN];
__device__ int    g_deg[NN];
__device__ int    g_csrc[NE2];
__device__ double g_stat[2];

// ---- fused prep: h0 build + edge count + stat init + all weight converts ---
__global__ void k_prep(const float* __restrict__ x, const float* __restrict__ cf,
        const int* __restrict__ ei,
        const float* __restrict__ Wlf, const float* __restrict__ Wrf,
        const float* __restrict__ Wli, const float* __restrict__ Wri,
        const float* __restrict__ Wll, const float* __restrict__ Wrl) {
    int bid = blockIdx.x;
    if (bid < PREPB) {
        int i = bid*256 + threadIdx.x;
        if (i == 0) { g_stat[0] = 0.0; g_stat[1] = 0.0; }
        if (i < NE) atomicAdd(&g_deg[ei[NE + i]], 1);
        if (i >= NN*128) return;
        int row = i >> 7;
        int col = i & 127;
        float v = 0.f;
        if (col < 32)      v = x[row*32 + col];
        else if (col < 96) v = cf[(row/27)*64 + (col - 32)];
        __nv_bfloat16 h = __float2bfloat16(v);
        g_ah[i] = h;
        g_al[i] = __float2bfloat16(v - __bfloat162float(h));
        if (col < 96) g_res[row*96 + col] = v;
    } else {
        int j = bid - PREPB;
        int s = j / 576;
        int l = s >> 1, m = s & 1;
        int K    = (l == 0) ? 96  : 384;
        int Kpad = (l == 0) ? 128 : 384;
        int Nc   = (l == 4) ? 96  : 384;
        const float* src;
        if (l == 0)      src = m ? Wrf : Wlf;
        else if (l == 4) src = m ? Wrl : Wll;
        else             src = (m ? Wri : Wli) + (size_t)(l-1)*WSLOT;
        int i = (j - s*576)*256 + threadIdx.x;
        if (i >= Nc*Kpad) return;
        int n = i / Kpad, k = i - n*Kpad;
        float v = (k < K) ? src[(size_t)k*Nc + n] : 0.f;
        __nv_bfloat16 h = __float2bfloat16(v);
        g_wbh[(size_t)s*WSLOT + i] = h;
        g_wbl[(size_t)s*WSLOT + i] = __float2bfloat16(v - __bfloat162float(h));
    }
}

// ---- single-block scan (adds +1 self loop per node, re-zeros g_deg) --------
__global__ void k_scan() {
    __shared__ int wsum[32], wbase[32];
    __shared__ int stot;
    int tid = threadIdx.x, lane = tid & 31, wid = tid >> 5;
    int base = tid*7;
    int v[7]; int s = 0;
    #pragma unroll
    for (int j = 0; j < 7; j++) {
        int i = base + j;
        v[j] = (i < NN) ? (g_deg[i] + 1) : 0;
        s += v[j];
    }
    int incl = s;
    #pragma unroll
    for (int o = 1; o < 32; o <<= 1) {
        int t = __shfl_up_sync(0xffffffffu, incl, o);
        if (lane >= o) incl += t;
    }
    if (lane == 31) wsum[wid] = incl;
    __syncthreads();
    if (wid == 0) {
        int x = wsum[lane];
        int xi = x;
        #pragma unroll
        for (int o = 1; o < 32; o <<= 1) {
            int t = __shfl_up_sync(0xffffffffu, xi, o);
            if (lane >= o) xi += t;
        }
        wbase[lane] = xi - x;
        if (lane == 31) stot = xi;
    }
    __syncthreads();
    int ex = wbase[wid] + (incl - s);
    #pragma unroll
    for (int j = 0; j < 7; j++) {
        int i = base + j;
        if (i < NN) { g_off[i] = ex; g_cur[i] = ex; g_deg[i] = 0; }
        ex += v[j];
    }
    if (tid == 0) g_off[NN] = stot;
}

__global__ void k_scatter(const int* __restrict__ ei) {
    int i = blockIdx.x*blockDim.x + threadIdx.x;
    if (i >= NE2) return;
    int s, d;
    if (i < NE) { s = ei[i]; d = ei[NE + i]; }
    else        { s = i - NE; d = s; }
    int pos = atomicAdd(&g_cur[d], 1);
    g_csrc[pos] = s;
}

// ---- cp.async double-buffered mma.sync bf16 split GEMM, 128x64 tiles -------
#define KC 32
#define APITCH 40
#define TILEA (128*APITCH)          // 5120 elems (10240 B)
#define TILEBN (64*APITCH)          // 2560 elems (5120 B)
#define SMEM_GEMM ((4*TILEA + 4*TILEBN)*2)   // 61440 B -> 3 CTAs/SM

__device__ __forceinline__ void mma16816(float* c, const uint32_t* a,
                                         uint32_t b0, uint32_t b1) {
    asm volatile(
        "mma.sync.aligned.m16n8k16.row.col.f32.bf16.bf16.f32 "
        "{%0,%1,%2,%3},{%4,%5,%6,%7},{%8,%9},{%0,%1,%2,%3};"
        : "+f"(c[0]), "+f"(c[1]), "+f"(c[2]), "+f"(c[3])
        : "r"(a[0]), "r"(a[1]), "r"(a[2]), "r"(a[3]), "r"(b0), "r"(b1));
}
__device__ __forceinline__ void cpa16(uint32_t dst, const void* src, int nbytes) {
    asm volatile("cp.async.cg.shared.global [%0], [%1], 16, %2;"
        :: "r"(dst), "l"(src), "r"(nbytes));
}

__global__ void __launch_bounds__(256, 3) k_mmagemm(
        const __nv_bfloat16* __restrict__ Ah, const __nv_bfloat16* __restrict__ Al,
        const __nv_bfloat16* __restrict__ B1h, const __nv_bfloat16* __restrict__ B1l,
        const __nv_bfloat16* __restrict__ B2h, const __nv_bfloat16* __restrict__ B2l,
        float* __restrict__ C1, float* __restrict__ C2,
        int Kg, int Nc, int ntiles) {
    extern __shared__ __nv_bfloat16 smg[];
    __nv_bfloat16* Asm = smg;                 // [stage][hl] x TILEA
    __nv_bfloat16* Bsm = smg + 4*TILEA;       // [stage][hl] x TILEBN
    int tid = threadIdx.x, wid = tid >> 5, lane = tid & 31;
    int mat = blockIdx.x / ntiles;
    int n0  = (blockIdx.x - mat*ntiles) * 64;
    int m0  = blockIdx.y * 128;
    const __nv_bfloat16* Bh = mat ? B2h : B1h;
    const __nv_bfloat16* Bl = mat ? B2l : B1l;
    float* C = mat ? C2 : C1;
    int warp_m = wid & 3, warp_n = wid >> 2;
    int gid = lane >> 2, tig = lane & 3;

    uint32_t aBase, bBase;
    asm("{ .reg .u64 t; cvta.to.shared.u64 t, %1; cvt.u32.u64 %0, t; }"
        : "=r"(aBase) : "l"(Asm));
    asm("{ .reg .u64 t; cvta.to.shared.u64 t, %1; cvt.u32.u64 %0, t; }"
        : "=r"(bBase) : "l"(Bsm));

    float acc[2][4][4];
    #pragma unroll
    for (int mt = 0; mt < 2; mt++)
        #pragma unroll
        for (int nt = 0; nt < 4; nt++)
            #pragma unroll
            for (int j = 0; j < 4; j++) acc[mt][nt][j] = 0.f;

    int nch = Kg / KC;
    int rg = tid >> 2, qg = tid & 3;
    #define ISSUE(c_, st_) do { \
        int _k0 = (c_)*KC; \
        uint32_t _sa = (uint32_t)(st_)*(2*TILEA*2); \
        uint32_t _sb = (uint32_t)(st_)*(2*TILEBN*2); \
        _Pragma("unroll") \
        for (int _j = 0; _j < 2; _j++) { \
            int _r = rg + _j*64; \
            uint32_t _off = _sa + (uint32_t)(_r*APITCH + qg*8)*2; \
            size_t _ga = (size_t)(m0 + _r)*Kg + _k0 + qg*8; \
            cpa16(aBase + _off,           Ah + _ga, 16); \
            cpa16(aBase + _off + TILEA*2, Al + _ga, 16); \
        } \
        { \
            uint32_t _off = _sb + (uint32_t)(rg*APITCH + qg*8)*2; \
            int _vb = (n0 + rg < Nc) ? 16 : 0; \
            size_t _gb = (size_t)(n0 + rg)*Kg + _k0 + qg*8; \
            cpa16(bBase + _off,            Bh + _gb, _vb); \
            cpa16(bBase + _off + TILEBN*2, Bl + _gb, _vb); \
        } \
        asm volatile("cp.async.commit_group;"); \
    } while (0)

    ISSUE(0, 0);
    for (int c = 0; c < nch; c++) {
        int st = c & 1;
        if (c + 1 < nch) {
            ISSUE(c + 1, st ^ 1);
            asm volatile("cp.async.wait_group 1;");
        } else {
            asm volatile("cp.async.wait_group 0;");
        }
        __syncthreads();
        const __nv_bfloat16* Ast0 = Asm + st*2*TILEA;
        const __nv_bfloat16* Bst0 = Bsm + st*2*TILEBN;
        #pragma unroll
        for (int ks = 0; ks < 2; ks++) {
            int cb = ks*16 + tig*2;
            uint32_t afr[2][2][4];
            #pragma unroll
            for (int mt = 0; mt < 2; mt++) {
                int r0 = warp_m*32 + mt*16 + gid;
                #pragma unroll
                for (int hl = 0; hl < 2; hl++) {
                    const __nv_bfloat16* bp = Ast0 + hl*TILEA;
                    afr[mt][hl][0] = *(const uint32_t*)&bp[r0*APITCH + cb];
                    afr[mt][hl][1] = *(const uint32_t*)&bp[(r0+8)*APITCH + cb];
                    afr[mt][hl][2] = *(const uint32_t*)&bp[r0*APITCH + cb + 8];
                    afr[mt][hl][3] = *(const uint32_t*)&bp[(r0+8)*APITCH + cb + 8];
                }
            }
            #pragma unroll
            for (int nt = 0; nt < 4; nt++) {
                int n = warp_n*32 + nt*8 + gid;
                uint32_t bh0 = *(const uint32_t*)&Bst0[n*APITCH + cb];
                uint32_t bh1 = *(const uint32_t*)&Bst0[n*APITCH + cb + 8];
                uint32_t bl0 = *(const uint32_t*)&Bst0[TILEBN + n*APITCH + cb];
                uint32_t bl1 = *(const uint32_t*)&Bst0[TILEBN + n*APITCH + cb + 8];
                #pragma unroll
                for (int mt = 0; mt < 2; mt++) {
                    mma16816(acc[mt][nt], afr[mt][0], bh0, bh1);
                    mma16816(acc[mt][nt], afr[mt][0], bl0, bl1);
                    mma16816(acc[mt][nt], afr[mt][1], bh0, bh1);
                }
            }
        }
        __syncthreads();
    }

    #pragma unroll
    for (int nt = 0; nt < 4; nt++) {
        int col = n0 + warp_n*32 + nt*8 + tig*2;
        if (col >= Nc) continue;
        #pragma unroll
        for (int mt = 0; mt < 2; mt++) {
            int row = m0 + warp_m*32 + mt*16 + gid;
            *(float2*)(C + (size_t)row*Nc + col) =
                make_float2(acc[mt][nt][0], acc[mt][nt][1]);
            *(float2*)(C + (size_t)(row+8)*Nc + col) =
                make_float2(acc[mt][nt][2], acc[mt][nt][3]);
        }
    }
}

// ---- attention logits: block per dst node, 2-edge unroll for MLP -----------
__global__ void k_logits2(const float* __restrict__ xl, const float* __restrict__ xr,
        const float* __restrict__ att, int H) {
    int b = blockIdx.x;
    int h = threadIdx.x >> 5, lane = threadIdx.x & 31;
    int W = H * 96;
    int c = h*96 + lane;
    float xr0 = xr[(size_t)b*W + c];
    float xr1 = xr[(size_t)b*W + c + 32];
    float xr2 = xr[(size_t)b*W + c + 64];
    float at0 = __ldg(att + c);
    float at1 = __ldg(att + c + 32);
    float at2 = __ldg(att + c + 64);
    int e  = g_off[b];
    int e1 = g_off[b+1];
    for (; e + 2 <= e1; e += 2) {
        const float* p0 = xl + (size_t)g_csrc[e]  *W + h*96;
        const float* p1 = xl + (size_t)g_csrc[e+1]*W + h*96;
        float a0 = p0[lane], a1 = p0[lane+32], a2 = p0[lane+64];
        float b0 = p1[lane], b1 = p1[lane+32], b2 = p1[lane+64];
        a0 += xr0; a1 += xr1; a2 += xr2;
        b0 += xr0; b1 += xr1; b2 += xr2;
        a0 = a0 > 0.f ? a0 : 0.2f*a0;
        a1 = a1 > 0.f ? a1 : 0.2f*a1;
        a2 = a2 > 0.f ? a2 : 0.2f*a2;
        b0 = b0 > 0.f ? b0 : 0.2f*b0;
        b1 = b1 > 0.f ? b1 : 0.2f*b1;
        b2 = b2 > 0.f ? b2 : 0.2f*b2;
        float u = fmaf(at0, a0, fmaf(at1, a1, at2*a2));
        float v = fmaf(at0, b0, fmaf(at1, b1, at2*b2));
        #pragma unroll
        for (int o = 16; o; o >>= 1) {
            u += __shfl_xor_sync(0xffffffffu, u, o);
            v += __shfl_xor_sync(0xffffffffu, v, o);
        }
        if (lane == 0) {
            g_logits[(size_t)e*H + h]     = u;
            g_logits[(size_t)(e+1)*H + h] = v;
        }
    }
    if (e < e1) {
        const float* p0 = xl + (size_t)g_csrc[e]*W + h*96;
        float a0 = p0[lane] + xr0, a1 = p0[lane+32] + xr1, a2 = p0[lane+64] + xr2;
        a0 = a0 > 0.f ? a0 : 0.2f*a0;
        a1 = a1 > 0.f ? a1 : 0.2f*a1;
        a2 = a2 > 0.f ? a2 : 0.2f*a2;
        float u = fmaf(at0, a0, fmaf(at1, a1, at2*a2));
        #pragma unroll
        for (int o = 16; o; o >>= 1) u += __shfl_xor_sync(0xffffffffu, u, o);
        if (lane == 0) g_logits[(size_t)e*H + h] = u;
    }
}

// ---- per-dst softmax + aggregation; epilogue writes bf16 hi/lo or fp32 -----
__global__ void k_agg(const float* __restrict__ xl, const float* __restrict__ bias,
        float* __restrict__ outF, __nv_bfloat16* __restrict__ oh,
        __nv_bfloat16* __restrict__ ol, int H, int flags) {
    int b   = blockIdx.x;
    int tid = threadIdx.x;
    int W   = blockDim.x;
    int h   = tid / 96;
    int lane = tid & 31, wid = tid >> 5;
    int e0 = g_off[b], deg = g_off[b+1] - e0;

    __shared__ float s_m[4], s_id[4];
    if (wid < H) {
        float m = -1e30f;
        for (int i = lane; i < deg; i += 32)
            m = fmaxf(m, g_logits[(size_t)(e0+i)*H + wid]);
        #pragma unroll
        for (int o = 16; o; o >>= 1) m = fmaxf(m, __shfl_xor_sync(0xffffffffu, m, o));
        float ss = 0.f;
        for (int i = lane; i < deg; i += 32)
            ss += __expf(g_logits[(size_t)(e0+i)*H + wid] - m);
        #pragma unroll
        for (int o = 16; o; o >>= 1) ss += __shfl_xor_sync(0xffffffffu, ss, o);
        if (lane == 0) { s_m[wid] = m; s_id[wid] = 1.f/ss; }
    }
    __syncthreads();

    __shared__ float s_alpha[4*96];
    __shared__ int   s_src[96];
    float a0 = 0.f, a1 = 0.f;
    for (int base = 0; base < deg; base += 96) {
        int cn = min(96, deg - base);
        if (tid < cn) s_src[tid] = g_csrc[e0 + base + tid];
        if (wid < H) {
            float m = s_m[wid], id = s_id[wid];
            for (int i = lane; i < cn; i += 32)
                s_alpha[wid*96 + i] =
                    __expf(g_logits[(size_t)(e0 + base + i)*H + wid] - m) * id;
        }
        __syncthreads();
        int i = 0;
        for (; i + 2 <= cn; i += 2) {
            a0 = fmaf(s_alpha[h*96 + i],     xl[(size_t)s_src[i]  *W + tid], a0);
            a1 = fmaf(s_alpha[h*96 + i + 1], xl[(size_t)s_src[i+1]*W + tid], a1);
        }
        if (i < cn) a0 = fmaf(s_alpha[h*96 + i], xl[(size_t)s_src[i]*W + tid], a0);
        __syncthreads();
    }
    float o = a0 + a1 + __ldg(bias + tid);
    o = o > 0.f ? o : 0.01f*o;
    size_t oi = (size_t)b*W + tid;
    if (flags & 2) outF[oi] = o;
    if (flags & 1) {
        __nv_bfloat16 hi = __float2bfloat16(o);
        oh[oi] = hi;
        ol[oi] = __float2bfloat16(o - __bfloat162float(hi));
    }
}

// ---- residual add + LN statistics ------------------------------------------
__global__ void k_resred(const float* __restrict__ h5, float* __restrict__ buf) {
    double s = 0.0, s2 = 0.0;
    for (int i = blockIdx.x*blockDim.x + threadIdx.x; i < TOT;
         i += gridDim.x*blockDim.x) {
        float v = h5[i] + g_res[i];
        buf[i] = v;
        s  += (double)v;
        s2 += (double)v * (double)v;
    }
    #pragma unroll
    for (int o = 16; o; o >>= 1) {
        s  += __shfl_xor_sync(0xffffffffu, s,  o);
        s2 += __shfl_xor_sync(0xffffffffu, s2, o);
    }
    __shared__ double sh[8], sh2[8];
    int lane = threadIdx.x & 31, wid = threadIdx.x >> 5;
    if (lane == 0) { sh[wid] = s; sh2[wid] = s2; }
    __syncthreads();
    if (wid == 0) {
        int nw = blockDim.x >> 5;
        s  = (lane < nw) ? sh[lane]  : 0.0;
        s2 = (lane < nw) ? sh2[lane] : 0.0;
        #pragma unroll
        for (int o = 4; o; o >>= 1) {
            s  += __shfl_xor_sync(0xffffffffu, s,  o);
            s2 += __shfl_xor_sync(0xffffffffu, s2, o);
        }
        if (lane == 0) { atomicAdd(&g_stat[0], s); atomicAdd(&g_stat[1], s2); }
    }
}

__global__ void k_final(const float* __restrict__ buf, const float* __restrict__ w,
        const float* __restrict__ bb, float* __restrict__ out) {
    double mu  = g_stat[0] / (double)TOT;
    double var = g_stat[1] / (double)TOT - mu*mu;
    float rs  = (float)(1.0 / sqrt(var + 1e-5));
    float fmu = (float)mu;
    for (int i = blockIdx.x*blockDim.x + threadIdx.x; i < TOT;
         i += gridDim.x*blockDim.x) {
        int c = i % DV;
        out[i] = (buf[i] - fmu) * rs * w[c] + bb[c];
    }
}

// ---- launch -----------------------------------------------------------------
extern "C" void kernel_launch(void* const* d_in, const int* in_sizes, int n_in,
                              void* d_out, int out_size) {
    const float* circ     = (const float*)d_in[0];
    const float* x        = (const float*)d_in[1];
    const int*   ei       = (const int*)d_in[2];
    const float* Wl_first = (const float*)d_in[3];
    const float* Wr_first = (const float*)d_in[4];
    const float* att_first= (const float*)d_in[5];
    const float* b_first  = (const float*)d_in[6];
    const float* Wl_inner = (const float*)d_in[7];
    const float* Wr_inner = (const float*)d_in[8];
    const float* att_inner= (const float*)d_in[9];
    const float* b_inner  = (const float*)d_in[10];
    const float* Wl_last  = (const float*)d_in[11];
    const float* Wr_last  = (const float*)d_in[12];
    const float* att_last = (const float*)d_in[13];
    const float* b_last   = (const float*)d_in[14];
    const float* ln_w     = (const float*)d_in[15];
    const float* ln_b     = (const float*)d_in[16];
    float*       outp     = (float*)d_out;

    float *hB, *buf, *xl, *xr;
    __nv_bfloat16 *ah, *al, *bh, *bl, *wbh, *wbl;
    cudaGetSymbolAddress((void**)&hB,  g_hB);
    cudaGetSymbolAddress((void**)&buf, g_buf);
    cudaGetSymbolAddress((void**)&xl,  g_xl);
    cudaGetSymbolAddress((void**)&xr,  g_xr);
    cudaGetSymbolAddress((void**)&ah,  g_ah);
    cudaGetSymbolAddress((void**)&al,  g_al);
    cudaGetSymbolAddress((void**)&bh,  g_bh);
    cudaGetSymbolAddress((void**)&bl,  g_bl);
    cudaGetSymbolAddress((void**)&wbh, g_wbh);
    cudaGetSymbolAddress((void**)&wbl, g_wbl);

    static int smem_set = 0;
    if (!smem_set) {
        cudaFuncSetAttribute(k_mmagemm,
            cudaFuncAttributeMaxDynamicSharedMemorySize, SMEM_GEMM);
        smem_set = 1;
    }

    k_prep   <<<PREPB + 5760, 256>>>(x, circ, ei, Wl_first, Wr_first,
                                     Wl_inner, Wr_inner, Wl_last, Wr_last);
    k_scan   <<<1, 1024>>>();
    k_scatter<<<(NE2 + 255)/256, 256>>>(ei);

    const float* atts[5] = {att_first, att_inner, att_inner + 384,
                            att_inner + 2*384, att_last};
    const float* bs[5]   = {b_first, b_inner, b_inner + 384, b_inner + 2*384, b_last};
    int Kpads[5] = {128, 384, 384, 384, 384};
    int Ncs[5]   = {384, 384, 384, 384, 96};
    int Hs[5]    = {4, 4, 4, 4, 1};

    __nv_bfloat16* inh = ah;  __nv_bfloat16* inl = al;
    __nv_bfloat16* oth = bh;  __nv_bfloat16* otl = bl;
    for (int l = 0; l < 5; l++) {
        int W = Hs[l]*96;
        int ntiles = (Ncs[l] + 63)/64;
        k_mmagemm<<<dim3(ntiles*2, NN/128), 256, SMEM_GEMM>>>(
            inh, inl,
            wbh + (size_t)(2*l)*WSLOT,   wbl + (size_t)(2*l)*WSLOT,
            wbh + (size_t)(2*l+1)*WSLOT, wbl + (size_t)(2*l+1)*WSLOT,
            xl, xr, Kpads[l], Ncs[l], ntiles);
        k_logits2<<<NN, 32*Hs[l]>>>(xl, xr, atts[l], Hs[l]);
        int flags = (l < 4) ? 1 : 2;
        k_agg<<<NN, W>>>(xl, bs[l], hB, oth, otl, Hs[l], flags);
        __nv_bfloat16* th = inh; inh = oth; oth = th;
        __nv_bfloat16* tl = inl; inl = otl; otl = tl;
    }
    k_resred<<<512, 256>>>(hB, buf);
    k_final <<<(TOT + 255)/256, 256>>>(buf, ln_w, ln_b, outp);
}

// round 16
// speedup vs baseline: 1.0646x; 1.0174x over previous
#include <cuda_runtime.h>
#include <cuda_bf16.h>
#include <math.h>
#include <stdint.h>

#define NN    6912                 // nodes
#define NE    82944                // edges (no self loops)
#define NE2   89856                // edges + self loops
#define DV    96                   // per-node feature width
#define TOT   (NN*DV)              // 663552 output elements
#define HIDW  384
#define WSLOT (384*384)
#define PREPB 3456                 // blocks for h0 region (NN*128/256)

// ---------------- scratch (static device globals; no allocs) ----------------
__device__ __align__(128) float g_hB[NN*DV];
__device__ __align__(128) float g_buf[NN*DV];
__device__ __align__(128) float g_res[TOT];
__device__ __align__(128) float g_xl[NN*HIDW];
__device__ __align__(128) float g_xr[NN*HIDW];
__device__ __align__(128) float g_logits[NE2*4];
__device__ __align__(128) __nv_bfloat16 g_ah[NN*HIDW];
__device__ __align__(128) __nv_bfloat16 g_al[NN*HIDW];
__device__ __align__(128) __nv_bfloat16 g_bh[NN*HIDW];
__device__ __align__(128) __nv_bfloat16 g_bl[NN*HIDW];
__device__ __align__(128) __nv_bfloat16 g_wbh[10*WSLOT];
__device__ __align__(128) __nv_bfloat16 g_wbl[10*WSLOT];
__device__ int    g_off[NN+1];
__device__ int    g_cur[NN];
__device__ int    g_deg[NN];
__device__ int    g_csrc[NE2];
__device__ double g_stat[2];

// ---- fused prep: h0 build + edge count + stat init + all weight converts ---
__global__ void k_prep(const float* __restrict__ x, const float* __restrict__ cf,
        const int* __restrict__ ei,
        const float* __restrict__ Wlf, const float* __restrict__ Wrf,
        const float* __restrict__ Wli, const float* __restrict__ Wri,
        const float* __restrict__ Wll, const float* __restrict__ Wrl) {
    int bid = blockIdx.x;
    if (bid < PREPB) {
        int i = bid*256 + threadIdx.x;
        if (i == 0) { g_stat[0] = 0.0; g_stat[1] = 0.0; }
        if (i < NE) atomicAdd(&g_deg[ei[NE + i]], 1);
        if (i >= NN*128) return;
        int row = i >> 7;
        int col = i & 127;
        float v = 0.f;
        if (col < 32)      v = x[row*32 + col];
        else if (col < 96) v = cf[(row/27)*64 + (col - 32)];
        __nv_bfloat16 h = __float2bfloat16(v);
        g_ah[i] = h;
        g_al[i] = __float2bfloat16(v - __bfloat162float(h));
        if (col < 96) g_res[row*96 + col] = v;
    } else {
        int j = bid - PREPB;
        int s = j / 576;
        int l = s >> 1, m = s & 1;
        int K    = (l == 0) ? 96  : 384;
        int Kpad = (l == 0) ? 128 : 384;
        int Nc   = (l == 4) ? 96  : 384;
        const float* src;
        if (l == 0)      src = m ? Wrf : Wlf;
        else if (l == 4) src = m ? Wrl : Wll;
        else             src = (m ? Wri : Wli) + (size_t)(l-1)*WSLOT;
        int i = (j - s*576)*256 + threadIdx.x;
        if (i >= Nc*Kpad) return;
        int n = i / Kpad, k = i - n*Kpad;
        float v = (k < K) ? src[(size_t)k*Nc + n] : 0.f;
        __nv_bfloat16 h = __float2bfloat16(v);
        g_wbh[(size_t)s*WSLOT + i] = h;
        g_wbl[(size_t)s*WSLOT + i] = __float2bfloat16(v - __bfloat162float(h));
    }
}

// ---- single-block scan (adds +1 self loop per node, re-zeros g_deg) --------
__global__ void k_scan() {
    __shared__ int wsum[32], wbase[32];
    __shared__ int stot;
    int tid = threadIdx.x, lane = tid & 31, wid = tid >> 5;
    int base = tid*7;
    int v[7]; int s = 0;
    #pragma unroll
    for (int j = 0; j < 7; j++) {
        int i = base + j;
        v[j] = (i < NN) ? (g_deg[i] + 1) : 0;
        s += v[j];
    }
    int incl = s;
    #pragma unroll
    for (int o = 1; o < 32; o <<= 1) {
        int t = __shfl_up_sync(0xffffffffu, incl, o);
        if (lane >= o) incl += t;
    }
    if (lane == 31) wsum[wid] = incl;
    __syncthreads();
    if (wid == 0) {
        int x = wsum[lane];
        int xi = x;
        #pragma unroll
        for (int o = 1; o < 32; o <<= 1) {
            int t = __shfl_up_sync(0xffffffffu, xi, o);
            if (lane >= o) xi += t;
        }
        wbase[lane] = xi - x;
        if (lane == 31) stot = xi;
    }
    __syncthreads();
    int ex = wbase[wid] + (incl - s);
    #pragma unroll
    for (int j = 0; j < 7; j++) {
        int i = base + j;
        if (i < NN) { g_off[i] = ex; g_cur[i] = ex; g_deg[i] = 0; }
        ex += v[j];
    }
    if (tid == 0) g_off[NN] = stot;
}

__global__ void k_scatter(const int* __restrict__ ei) {
    int i = blockIdx.x*blockDim.x + threadIdx.x;
    if (i >= NE2) return;
    int s, d;
    if (i < NE) { s = ei[i]; d = ei[NE + i]; }
    else        { s = i - NE; d = s; }
    int pos = atomicAdd(&g_cur[d], 1);
    g_csrc[pos] = s;
}

// ---- cp.async + ldmatrix double-buffered mma.sync split GEMM, 128x64 -------
#define KC 32
#define APITCH 40
#define TILEA (128*APITCH)          // 5120 elems (10240 B)
#define TILEBN (64*APITCH)          // 2560 elems (5120 B)
#define SMEM_GEMM ((4*TILEA + 4*TILEBN)*2)   // 61440 B -> 3 CTAs/SM

__device__ __forceinline__ void mma16816(float* c, const uint32_t* a,
                                         uint32_t b0, uint32_t b1) {
    asm volatile(
        "mma.sync.aligned.m16n8k16.row.col.f32.bf16.bf16.f32 "
        "{%0,%1,%2,%3},{%4,%5,%6,%7},{%8,%9},{%0,%1,%2,%3};"
        : "+f"(c[0]), "+f"(c[1]), "+f"(c[2]), "+f"(c[3])
        : "r"(a[0]), "r"(a[1]), "r"(a[2]), "r"(a[3]), "r"(b0), "r"(b1));
}
__device__ __forceinline__ void cpa16(uint32_t dst, const void* src, int nbytes) {
    asm volatile("cp.async.cg.shared.global [%0], [%1], 16, %2;"
        :: "r"(dst), "l"(src), "r"(nbytes));
}
__device__ __forceinline__ void ldsm4(uint32_t* r, uint32_t addr) {
    asm volatile("ldmatrix.sync.aligned.m8n8.x4.shared.b16 {%0,%1,%2,%3}, [%4];"
        : "=r"(r[0]), "=r"(r[1]), "=r"(r[2]), "=r"(r[3]) : "r"(addr));
}

__global__ void __launch_bounds__(256, 3) k_mmagemm(
        const __nv_bfloat16* __restrict__ Ah, const __nv_bfloat16* __restrict__ Al,
        const __nv_bfloat16* __restrict__ B1h, const __nv_bfloat16* __restrict__ B1l,
        const __nv_bfloat16* __restrict__ B2h, const __nv_bfloat16* __restrict__ B2l,
        float* __restrict__ C1, float* __restrict__ C2,
        int Kg, int Nc, int ntiles) {
    extern __shared__ __nv_bfloat16 smg[];
    __nv_bfloat16* Asm = smg;                 // [stage][hl] x TILEA
    __nv_bfloat16* Bsm = smg + 4*TILEA;       // [stage][hl] x TILEBN
    int tid = threadIdx.x, wid = tid >> 5, lane = tid & 31;
    int mat = blockIdx.x / ntiles;
    int n0  = (blockIdx.x - mat*ntiles) * 64;
    int m0  = blockIdx.y * 128;
    const __nv_bfloat16* Bh = mat ? B2h : B1h;
    const __nv_bfloat16* Bl = mat ? B2l : B1l;
    float* C = mat ? C2 : C1;
    int warp_m = wid & 3, warp_n = wid >> 2;
    int gid = lane >> 2, tig = lane & 3;

    uint32_t aBase, bBase;
    asm("{ .reg .u64 t; cvta.to.shared.u64 t, %1; cvt.u32.u64 %0, t; }"
        : "=r"(aBase) : "l"(Asm));
    asm("{ .reg .u64 t; cvta.to.shared.u64 t, %1; cvt.u32.u64 %0, t; }"
        : "=r"(bBase) : "l"(Bsm));

    // ldmatrix per-lane byte offsets (within one hl tile)
    // A .x4: matrices (rows r..r+7, k 0..7),(r+8..r+15, 0..7),(r..r+7, 8..15),(r+8..,8..15)
    uint32_t aOff[2];
    #pragma unroll
    for (int mt = 0; mt < 2; mt++) {
        int row = warp_m*32 + mt*16 + (lane & 15);
        int col = (lane >> 4) * 8;
        aOff[mt] = (uint32_t)(row*APITCH + col) * 2;
    }
    // B .x4 over an nt-pair p: matrices (nt=2p rows, k0..7),(2p,8..15),(2p+1,0..7),(2p+1,8..15)
    uint32_t bOff[2];
    #pragma unroll
    for (int p = 0; p < 2; p++) {
        int row = warp_n*32 + (p*2 + (lane >> 4))*8 + (lane & 7);
        int col = ((lane >> 3) & 1) * 8;
        bOff[p] = (uint32_t)(row*APITCH + col) * 2;
    }

    float acc[2][4][4];
    #pragma unroll
    for (int mt = 0; mt < 2; mt++)
        #pragma unroll
        for (int nt = 0; nt < 4; nt++)
            #pragma unroll
            for (int j = 0; j < 4; j++) acc[mt][nt][j] = 0.f;

    int nch = Kg / KC;
    int rg = tid >> 2, qg = tid & 3;
    #define ISSUE(c_, st_) do { \
        int _k0 = (c_)*KC; \
        uint32_t _sa = (uint32_t)(st_)*(2*TILEA*2); \
        uint32_t _sb = (uint32_t)(st_)*(2*TILEBN*2); \
        _Pragma("unroll") \
        for (int _j = 0; _j < 2; _j++) { \
            int _r = rg + _j*64; \
            uint32_t _off = _sa + (uint32_t)(_r*APITCH + qg*8)*2; \
            size_t _ga = (size_t)(m0 + _r)*Kg + _k0 + qg*8; \
            cpa16(aBase + _off,           Ah + _ga, 16); \
            cpa16(aBase + _off + TILEA*2, Al + _ga, 16); \
        } \
        { \
            uint32_t _off = _sb + (uint32_t)(rg*APITCH + qg*8)*2; \
            int _vb = (n0 + rg < Nc) ? 16 : 0; \
            size_t _gb = (size_t)(n0 + rg)*Kg + _k0 + qg*8; \
            cpa16(bBase + _off,            Bh + _gb, _vb); \
            cpa16(bBase + _off + TILEBN*2, Bl + _gb, _vb); \
        } \
        asm volatile("cp.async.commit_group;"); \
    } while (0)

    ISSUE(0, 0);
    for (int c = 0; c < nch; c++) {
        int st = c & 1;
        if (c + 1 < nch) {
            ISSUE(c + 1, st ^ 1);
            asm volatile("cp.async.wait_group 1;");
        } else {
            asm volatile("cp.async.wait_group 0;");
        }
        __syncthreads();
        uint32_t aSt = aBase + (uint32_t)st*(2*TILEA*2);
        uint32_t bSt = bBase + (uint32_t)st*(2*TILEBN*2);
        #pragma unroll
        for (int ks = 0; ks < 2; ks++) {
            uint32_t kB = (uint32_t)ks*32;          // ks*16 bf16 = 32 bytes
            uint32_t afr[2][2][4];                   // [mt][hl]
            #pragma unroll
            for (int mt = 0; mt < 2; mt++) {
                ldsm4(afr[mt][0], aSt + aOff[mt] + kB);
                ldsm4(afr[mt][1], aSt + TILEA*2 + aOff[mt] + kB);
            }
            uint32_t bfr[2][2][4];                   // [p][hl] = {b0,b1 nt=2p; b0,b1 nt=2p+1}
            #pragma unroll
            for (int p = 0; p < 2; p++) {
                ldsm4(bfr[p][0], bSt + bOff[p] + kB);
                ldsm4(bfr[p][1], bSt + TILEBN*2 + bOff[p] + kB);
            }
            #pragma unroll
            for (int nt = 0; nt < 4; nt++) {
                uint32_t bh0 = bfr[nt>>1][0][(nt&1)*2];
                uint32_t bh1 = bfr[nt>>1][0][(nt&1)*2 + 1];
                uint32_t bl0 = bfr[nt>>1][1][(nt&1)*2];
                uint32_t bl1 = bfr[nt>>1][1][(nt&1)*2 + 1];
                #pragma unroll
                for (int mt = 0; mt < 2; mt++) {
                    mma16816(acc[mt][nt], afr[mt][0], bh0, bh1);
                    mma16816(acc[mt][nt], afr[mt][0], bl0, bl1);
                    mma16816(acc[mt][nt], afr[mt][1], bh0, bh1);
                }
            }
        }
        __syncthreads();
    }

    #pragma unroll
    for (int nt = 0; nt < 4; nt++) {
        int col = n0 + warp_n*32 + nt*8 + tig*2;
        if (col >= Nc) continue;
        #pragma unroll
        for (int mt = 0; mt < 2; mt++) {
            int row = m0 + warp_m*32 + mt*16 + gid;
            *(float2*)(C + (size_t)row*Nc + col) =
                make_float2(acc[mt][nt][0], acc[mt][nt][1]);
            *(float2*)(C + (size_t)(row+8)*Nc + col) =
                make_float2(acc[mt][nt][2], acc[mt][nt][3]);
        }
    }
}

// ---- attention logits: block per dst node, 2-edge unroll for MLP -----------
__global__ void k_logits2(const float* __restrict__ xl, const float* __restrict__ xr,
        const float* __restrict__ att, int H) {
    int b = blockIdx.x;
    int h = threadIdx.x >> 5, lane = threadIdx.x & 31;
    int W = H * 96;
    int c = h*96 + lane;
    float xr0 = xr[(size_t)b*W + c];
    float xr1 = xr[(size_t)b*W + c + 32];
    float xr2 = xr[(size_t)b*W + c + 64];
    float at0 = __ldg(att + c);
    float at1 = __ldg(att + c + 32);
    float at2 = __ldg(att + c + 64);
    int e  = g_off[b];
    int e1 = g_off[b+1];
    for (; e + 2 <= e1; e += 2) {
        const float* p0 = xl + (size_t)g_csrc[e]  *W + h*96;
        const float* p1 = xl + (size_t)g_csrc[e+1]*W + h*96;
        float a0 = p0[lane], a1 = p0[lane+32], a2 = p0[lane+64];
        float b0 = p1[lane], b1 = p1[lane+32], b2 = p1[lane+64];
        a0 += xr0; a1 += xr1; a2 += xr2;
        b0 += xr0; b1 += xr1; b2 += xr2;
        a0 = a0 > 0.f ? a0 : 0.2f*a0;
        a1 = a1 > 0.f ? a1 : 0.2f*a1;
        a2 = a2 > 0.f ? a2 : 0.2f*a2;
        b0 = b0 > 0.f ? b0 : 0.2f*b0;
        b1 = b1 > 0.f ? b1 : 0.2f*b1;
        b2 = b2 > 0.f ? b2 : 0.2f*b2;
        float u = fmaf(at0, a0, fmaf(at1, a1, at2*a2));
        float v = fmaf(at0, b0, fmaf(at1, b1, at2*b2));
        #pragma unroll
        for (int o = 16; o; o >>= 1) {
            u += __shfl_xor_sync(0xffffffffu, u, o);
            v += __shfl_xor_sync(0xffffffffu, v, o);
        }
        if (lane == 0) {
            g_logits[(size_t)e*H + h]     = u;
            g_logits[(size_t)(e+1)*H + h] = v;
        }
    }
    if (e < e1) {
        const float* p0 = xl + (size_t)g_csrc[e]*W + h*96;
        float a0 = p0[lane] + xr0, a1 = p0[lane+32] + xr1, a2 = p0[lane+64] + xr2;
        a0 = a0 > 0.f ? a0 : 0.2f*a0;
        a1 = a1 > 0.f ? a1 : 0.2f*a1;
        a2 = a2 > 0.f ? a2 : 0.2f*a2;
        float u = fmaf(at0, a0, fmaf(at1, a1, at2*a2));
        #pragma unroll
        for (int o = 16; o; o >>= 1) u += __shfl_xor_sync(0xffffffffu, u, o);
        if (lane == 0) g_logits[(size_t)e*H + h] = u;
    }
}

// ---- per-dst softmax + aggregation; epilogue writes bf16 hi/lo or fp32 -----
__global__ void k_agg(const float* __restrict__ xl, const float* __restrict__ bias,
        float* __restrict__ outF, __nv_bfloat16* __restrict__ oh,
        __nv_bfloat16* __restrict__ ol, int H, int flags) {
    int b   = blockIdx.x;
    int tid = threadIdx.x;
    int W   = blockDim.x;
    int h   = tid / 96;
    int lane = tid & 31, wid = tid >> 5;
    int e0 = g_off[b], deg = g_off[b+1] - e0;

    __shared__ float s_m[4], s_id[4];
    if (wid < H) {
        float m = -1e30f;
        for (int i = lane; i < deg; i += 32)
            m = fmaxf(m, g_logits[(size_t)(e0+i)*H + wid]);
        #pragma unroll
        for (int o = 16; o; o >>= 1) m = fmaxf(m, __shfl_xor_sync(0xffffffffu, m, o));
        float ss = 0.f;
        for (int i = lane; i < deg; i += 32)
            ss += __expf(g_logits[(size_t)(e0+i)*H + wid] - m);
        #pragma unroll
        for (int o = 16; o; o >>= 1) ss += __shfl_xor_sync(0xffffffffu, ss, o);
        if (lane == 0) { s_m[wid] = m; s_id[wid] = 1.f/ss; }
    }
    __syncthreads();

    __shared__ float s_alpha[4*96];
    __shared__ int   s_src[96];
    float a0 = 0.f, a1 = 0.f;
    for (int base = 0; base < deg; base += 96) {
        int cn = min(96, deg - base);
        if (tid < cn) s_src[tid] = g_csrc[e0 + base + tid];
        if (wid < H) {
            float m = s_m[wid], id = s_id[wid];
            for (int i = lane; i < cn; i += 32)
                s_alpha[wid*96 + i] =
                    __expf(g_logits[(size_t)(e0 + base + i)*H + wid] - m) * id;
        }
        __syncthreads();
        int i = 0;
        for (; i + 2 <= cn; i += 2) {
            a0 = fmaf(s_alpha[h*96 + i],     xl[(size_t)s_src[i]  *W + tid], a0);
            a1 = fmaf(s_alpha[h*96 + i + 1], xl[(size_t)s_src[i+1]*W + tid], a1);
        }
        if (i < cn) a0 = fmaf(s_alpha[h*96 + i], xl[(size_t)s_src[i]*W + tid], a0);
        __syncthreads();
    }
    float o = a0 + a1 + __ldg(bias + tid);
    o = o > 0.f ? o : 0.01f*o;
    size_t oi = (size_t)b*W + tid;
    if (flags & 2) outF[oi] = o;
    if (flags & 1) {
        __nv_bfloat16 hi = __float2bfloat16(o);
        oh[oi] = hi;
        ol[oi] = __float2bfloat16(o - __bfloat162float(hi));
    }
}

// ---- residual add + LN statistics ------------------------------------------
__global__ void k_resred(const float* __restrict__ h5, float* __restrict__ buf) {
    double s = 0.0, s2 = 0.0;
    for (int i = blockIdx.x*blockDim.x + threadIdx.x; i < TOT;
         i += gridDim.x*blockDim.x) {
        float v = h5[i] + g_res[i];
        buf[i] = v;
        s  += (double)v;
        s2 += (double)v * (double)v;
    }
    #pragma unroll
    for (int o = 16; o; o >>= 1) {
        s  += __shfl_xor_sync(0xffffffffu, s,  o);
        s2 += __shfl_xor_sync(0xffffffffu, s2, o);
    }
    __shared__ double sh[8], sh2[8];
    int lane = threadIdx.x & 31, wid = threadIdx.x >> 5;
    if (lane == 0) { sh[wid] = s; sh2[wid] = s2; }
    __syncthreads();
    if (wid == 0) {
        int nw = blockDim.x >> 5;
        s  = (lane < nw) ? sh[lane]  : 0.0;
        s2 = (lane < nw) ? sh2[lane] : 0.0;
        #pragma unroll
        for (int o = 4; o; o >>= 1) {
            s  += __shfl_xor_sync(0xffffffffu, s,  o);
            s2 += __shfl_xor_sync(0xffffffffu, s2, o);
        }
        if (lane == 0) { atomicAdd(&g_stat[0], s); atomicAdd(&g_stat[1], s2); }
    }
}

__global__ void k_final(const float* __restrict__ buf, const float* __restrict__ w,
        const float* __restrict__ bb, float* __restrict__ out) {
    double mu  = g_stat[0] / (double)TOT;
    double var = g_stat[1] / (double)TOT - mu*mu;
    float rs  = (float)(1.0 / sqrt(var + 1e-5));
    float fmu = (float)mu;
    for (int i = blockIdx.x*blockDim.x + threadIdx.x; i < TOT;
         i += gridDim.x*blockDim.x) {
        int c = i % DV;
        out[i] = (buf[i] - fmu) * rs * w[c] + bb[c];
    }
}

// ---- launch -----------------------------------------------------------------
extern "C" void kernel_launch(void* const* d_in, const int* in_sizes, int n_in,
                              void* d_out, int out_size) {
    const float* circ     = (const float*)d_in[0];
    const float* x        = (const float*)d_in[1];
    const int*   ei       = (const int*)d_in[2];
    const float* Wl_first = (const float*)d_in[3];
    const float* Wr_first = (const float*)d_in[4];
    const float* att_first= (const float*)d_in[5];
    const float* b_first  = (const float*)d_in[6];
    const float* Wl_inner = (const float*)d_in[7];
    const float* Wr_inner = (const float*)d_in[8];
    const float* att_inner= (const float*)d_in[9];
    const float* b_inner  = (const float*)d_in[10];
    const float* Wl_last  = (const float*)d_in[11];
    const float* Wr_last  = (const float*)d_in[12];
    const float* att_last = (const float*)d_in[13];
    const float* b_last   = (const float*)d_in[14];
    const float* ln_w     = (const float*)d_in[15];
    const float* ln_b     = (const float*)d_in[16];
    float*       outp     = (float*)d_out;

    float *hB, *buf, *xl, *xr;
    __nv_bfloat16 *ah, *al, *bh, *bl, *wbh, *wbl;
    cudaGetSymbolAddress((void**)&hB,  g_hB);
    cudaGetSymbolAddress((void**)&buf, g_buf);
    cudaGetSymbolAddress((void**)&xl,  g_xl);
    cudaGetSymbolAddress((void**)&xr,  g_xr);
    cudaGetSymbolAddress((void**)&ah,  g_ah);
    cudaGetSymbolAddress((void**)&al,  g_al);
    cudaGetSymbolAddress((void**)&bh,  g_bh);
    cudaGetSymbolAddress((void**)&bl,  g_bl);
    cudaGetSymbolAddress((void**)&wbh, g_wbh);
    cudaGetSymbolAddress((void**)&wbl, g_wbl);

    static int smem_set = 0;
    if (!smem_set) {
        cudaFuncSetAttribute(k_mmagemm,
            cudaFuncAttributeMaxDynamicSharedMemorySize, SMEM_GEMM);
        smem_set = 1;
    }

    k_prep   <<<PREPB + 5760, 256>>>(x, circ, ei, Wl_first, Wr_first,
                                     Wl_inner, Wr_inner, Wl_last, Wr_last);
    k_scan   <<<1, 1024>>>();
    k_scatter<<<(NE2 + 255)/256, 256>>>(ei);

    const float* atts[5] = {att_first, att_inner, att_inner + 384,
                            att_inner + 2*384, att_last};
    const float* bs[5]   = {b_first, b_inner, b_inner + 384, b_inner + 2*384, b_last};
    int Kpads[5] = {128, 384, 384, 384, 384};
    int Ncs[5]   = {384, 384, 384, 384, 96};
    int Hs[5]    = {4, 4, 4, 4, 1};

    __nv_bfloat16* inh = ah;  __nv_bfloat16* inl = al;
    __nv_bfloat16* oth = bh;  __nv_bfloat16* otl = bl;
    for (int l = 0; l < 5; l++) {
        int W = Hs[l]*96;
        int ntiles = (Ncs[l] + 63)/64;
        k_mmagemm<<<dim3(ntiles*2, NN/128), 256, SMEM_GEMM>>>(
            inh, inl,
            wbh + (size_t)(2*l)*WSLOT,   wbl + (size_t)(2*l)*WSLOT,
            wbh + (size_t)(2*l+1)*WSLOT, wbl + (size_t)(2*l+1)*WSLOT,
            xl, xr, Kpads[l], Ncs[l], ntiles);
        k_logits2<<<NN, 32*Hs[l]>>>(xl, xr, atts[l], Hs[l]);
        int flags = (l < 4) ? 1 : 2;
        k_agg<<<NN, W>>>(xl, bs[l], hB, oth, otl, Hs[l], flags);
        __nv_bfloat16* th = inh; inh = oth; oth = th;
        __nv_bfloat16* tl = inl; inl = otl; otl = tl;
    }
    k_resred<<<512, 256>>>(hB, buf);
    k_final <<<(TOT + 255)/256, 256>>>(buf, ln_w, ln_b, outp);
}